// round 1
// baseline (speedup 1.0000x reference)
#include <cuda_runtime.h>
#include <cuda_bf16.h>
#include <mma.h>
#include <math.h>

using namespace nvcuda;

// Problem constants
#define NQ       65536
#define DIMIN    1024
#define DIMH     256
#define NCLUS    8

// GEMM tiling
#define BM 64
#define BK 32
#define ALD 40        // padded lds for A (multiple of 4, rows 16B-aligned)
#define BLD 40        // padded lds for B
#define NBLK (NQ / BM)    // 1024 blocks

// dynamic smem: max(As+Bs, hbuf) + cid
// As: 64*40 = 2560 fl, Bs: 256*40 = 10240 fl -> 12800 fl
// hbuf: 64*256 = 16384 fl ; cid: 64 ints after
#define SMEM_FLOATS (BM * DIMH)           // 16384
#define SMEM_BYTES  ((SMEM_FLOATS + BM) * 4)   // 65792

// Deterministic scratch (no allocations allowed)
__device__ float g_scratch[NBLK * NCLUS * DIMH];   // 8 MB, [block][cluster][col]
__device__ float g_seg[NCLUS * DIMH];              // segment sums
__device__ float g_hp[NCLUS * DIMH];               // h_path
__device__ float g_Ag[NCLUS];                      // attention logits

// ---------------------------------------------------------------------------
// K1: fused  h = relu(x @ W1^T + b1)  +  per-cluster column sums (per block)
// ---------------------------------------------------------------------------
__global__ __launch_bounds__(256)
void k_gemm_seg(const float* __restrict__ x,
                const int*   __restrict__ cid,
                const float* __restrict__ W1,
                const float* __restrict__ b1)
{
    extern __shared__ float sm[];
    float* As   = sm;                  // [64][40]
    float* Bs   = sm + BM * ALD;       // [256][40]
    float* hbuf = sm;                  // reused: [64][256]
    int*   cid_s = (int*)(sm + SMEM_FLOATS);

    const int tid  = threadIdx.x;
    const int warp = tid >> 5;
    const int wm   = warp >> 2;        // 0..1 (32-row slab)
    const int wn   = warp & 3;         // 0..3 (64-col slab)
    const int row0 = blockIdx.x * BM;

    wmma::fragment<wmma::accumulator, 16, 16, 8, float> acc[2][4];
    #pragma unroll
    for (int i = 0; i < 2; i++)
        #pragma unroll
        for (int j = 0; j < 4; j++)
            wmma::fill_fragment(acc[i][j], 0.0f);

    for (int k0 = 0; k0 < DIMIN; k0 += BK) {
        __syncthreads();
        // load A tile: 64 rows x 32 cols = 512 float4
        #pragma unroll
        for (int i = 0; i < 2; i++) {
            int lin = i * 256 + tid;
            int r   = lin >> 3;
            int c4  = (lin & 7) * 4;
            *(float4*)(As + r * ALD + c4) =
                *(const float4*)(x + (size_t)(row0 + r) * DIMIN + k0 + c4);
        }
        // load B tile (W1): 256 rows x 32 cols = 2048 float4
        #pragma unroll
        for (int i = 0; i < 8; i++) {
            int lin = i * 256 + tid;
            int n   = lin >> 3;
            int c4  = (lin & 7) * 4;
            *(float4*)(Bs + n * BLD + c4) =
                *(const float4*)(W1 + (size_t)n * DIMIN + k0 + c4);
        }
        __syncthreads();

        #pragma unroll
        for (int kk = 0; kk < BK; kk += 8) {
            wmma::fragment<wmma::matrix_a, 16, 16, 8, wmma::precision::tf32, wmma::row_major> af[2];
            wmma::fragment<wmma::matrix_b, 16, 16, 8, wmma::precision::tf32, wmma::col_major> bf[4];
            #pragma unroll
            for (int i = 0; i < 2; i++) {
                wmma::load_matrix_sync(af[i], As + (wm * 32 + i * 16) * ALD + kk, ALD);
                #pragma unroll
                for (int e = 0; e < af[i].num_elements; e++)
                    af[i].x[e] = wmma::__float_to_tf32(af[i].x[e]);
            }
            #pragma unroll
            for (int j = 0; j < 4; j++) {
                wmma::load_matrix_sync(bf[j], Bs + (wn * 64 + j * 16) * BLD + kk, BLD);
                #pragma unroll
                for (int e = 0; e < bf[j].num_elements; e++)
                    bf[j].x[e] = wmma::__float_to_tf32(bf[j].x[e]);
            }
            #pragma unroll
            for (int i = 0; i < 2; i++)
                #pragma unroll
                for (int j = 0; j < 4; j++)
                    wmma::mma_sync(acc[i][j], af[i], bf[j], acc[i][j]);
        }
    }

    __syncthreads();
    // dump tile to smem (reuse As/Bs region)
    #pragma unroll
    for (int i = 0; i < 2; i++)
        #pragma unroll
        for (int j = 0; j < 4; j++)
            wmma::store_matrix_sync(hbuf + (wm * 32 + i * 16) * DIMH + wn * 64 + j * 16,
                                    acc[i][j], DIMH, wmma::mem_row_major);
    if (tid < BM) cid_s[tid] = cid[row0 + tid];
    __syncthreads();

    // per-column, cluster-masked reduction over the 64 rows
    const float bt = b1[tid];
    float s[NCLUS];
    #pragma unroll
    for (int c = 0; c < NCLUS; c++) s[c] = 0.0f;

    #pragma unroll 4
    for (int r = 0; r < BM; r++) {
        float v = hbuf[r * DIMH + tid] + bt;
        v = fmaxf(v, 0.0f);
        int cd = cid_s[r];
        #pragma unroll
        for (int c = 0; c < NCLUS; c++)
            s[c] += (cd == c) ? v : 0.0f;
    }

    float* out = g_scratch + (size_t)blockIdx.x * (NCLUS * DIMH) + tid;
    #pragma unroll
    for (int c = 0; c < NCLUS; c++)
        out[c * DIMH] = s[c];
}

// ---------------------------------------------------------------------------
// K2: reduce 1024 block-partials -> g_seg[8*256]
// grid 64 x 256thr, each block handles 32 output columns
// ---------------------------------------------------------------------------
__global__ __launch_bounds__(256)
void k_reduce()
{
    const int g0 = blockIdx.x * 32;
    const int j  = threadIdx.x & 31;
    const int bs = threadIdx.x >> 5;    // 0..7 slice over blocks
    float s = 0.0f;
    #pragma unroll 4
    for (int b = bs; b < NBLK; b += 8)
        s += g_scratch[(size_t)b * (NCLUS * DIMH) + g0 + j];
    __shared__ float red[8][32];
    red[bs][j] = s;
    __syncthreads();
    if (bs == 0) {
        float t = 0.0f;
        #pragma unroll
        for (int c = 0; c < 8; c++) t += red[c][j];
        g_seg[g0 + j] = t;
    }
}

// ---------------------------------------------------------------------------
// K3a: per-cluster counts + means + h_path = relu(hc @ Wf^T + bf)
// grid 8 (one block per cluster) x 256thr
// ---------------------------------------------------------------------------
__global__ __launch_bounds__(256)
void k_head1(const int* __restrict__ cid,
             const float* __restrict__ Wf,
             const float* __restrict__ bfv)
{
    const int c = blockIdx.x, tid = threadIdx.x;
    __shared__ float hc_s[DIMH];
    __shared__ int cnt_s;

    int cnt = 0;
    for (int i = tid; i < NQ; i += 256)
        cnt += (cid[i] == c) ? 1 : 0;
    #pragma unroll
    for (int o = 16; o > 0; o >>= 1)
        cnt += __shfl_down_sync(0xffffffffu, cnt, o);
    if (tid == 0) cnt_s = 0;
    __syncthreads();
    if ((tid & 31) == 0) atomicAdd(&cnt_s, cnt);
    __syncthreads();

    const float denom = fmaxf((float)cnt_s, 1.0f);
    hc_s[tid] = g_seg[c * DIMH + tid] / denom;
    __syncthreads();

    float a = bfv[tid];
    const float4* w = (const float4*)(Wf + (size_t)tid * DIMH);
    #pragma unroll 8
    for (int k = 0; k < DIMH / 4; k++) {
        float4 wv = w[k];
        a += wv.x * hc_s[4 * k]     + wv.y * hc_s[4 * k + 1]
           + wv.z * hc_s[4 * k + 2] + wv.w * hc_s[4 * k + 3];
    }
    g_hp[c * DIMH + tid] = fmaxf(a, 0.0f);
}

// ---------------------------------------------------------------------------
// K3b: gated attention logits A[c] = Wc . (tanh(Wa hp + ba) * sig(Wb hp + bb)) + bc
// grid 8 x 256thr
// ---------------------------------------------------------------------------
__global__ __launch_bounds__(256)
void k_head2(const float* __restrict__ Wa, const float* __restrict__ ba,
             const float* __restrict__ Wb, const float* __restrict__ bb,
             const float* __restrict__ Wc, const float* __restrict__ bc)
{
    const int c = blockIdx.x, tid = threadIdx.x;
    __shared__ float hp_s[DIMH];
    __shared__ float red[256];
    hp_s[tid] = g_hp[c * DIMH + tid];
    __syncthreads();

    float aa = ba[tid];
    float gg = bb[tid];
    const float4* wa = (const float4*)(Wa + (size_t)tid * DIMH);
    const float4* wb = (const float4*)(Wb + (size_t)tid * DIMH);
    #pragma unroll 8
    for (int k = 0; k < DIMH / 4; k++) {
        float4 av = wa[k], bv = wb[k];
        float h0 = hp_s[4 * k], h1 = hp_s[4 * k + 1], h2 = hp_s[4 * k + 2], h3 = hp_s[4 * k + 3];
        aa += av.x * h0 + av.y * h1 + av.z * h2 + av.w * h3;
        gg += bv.x * h0 + bv.y * h1 + bv.z * h2 + bv.w * h3;
    }
    float t = tanhf(aa);
    float sgm = 1.0f / (1.0f + expf(-gg));
    red[tid] = t * sgm * Wc[tid];
    __syncthreads();
    #pragma unroll
    for (int o = 128; o > 0; o >>= 1) {
        if (tid < o) red[tid] += red[tid + o];
        __syncthreads();
    }
    if (tid == 0) g_Ag[c] = red[0] + bc[0];
}

// ---------------------------------------------------------------------------
// K3c: softmax over 8 logits + weighted sum of h_path -> out[256]
// ---------------------------------------------------------------------------
__global__ __launch_bounds__(256)
void k_final(float* __restrict__ out)
{
    const int tid = threadIdx.x;
    float av[NCLUS];
    float m = -1e30f;
    #pragma unroll
    for (int c = 0; c < NCLUS; c++) { av[c] = g_Ag[c]; m = fmaxf(m, av[c]); }
    float ssum = 0.0f;
    #pragma unroll
    for (int c = 0; c < NCLUS; c++) { av[c] = expf(av[c] - m); ssum += av[c]; }
    float o = 0.0f;
    #pragma unroll
    for (int c = 0; c < NCLUS; c++)
        o += av[c] * g_hp[c * DIMH + tid];
    out[tid] = o / ssum;
}

// ---------------------------------------------------------------------------
extern "C" void kernel_launch(void* const* d_in, const int* in_sizes, int n_in,
                              void* d_out, int out_size)
{
    const float* x   = (const float*)d_in[0];
    const int*   cid = (const int*)  d_in[1];
    const float* W1  = (const float*)d_in[2];
    const float* b1  = (const float*)d_in[3];
    const float* Wf  = (const float*)d_in[4];
    const float* bf  = (const float*)d_in[5];
    const float* Wa  = (const float*)d_in[6];
    const float* ba  = (const float*)d_in[7];
    const float* Wb  = (const float*)d_in[8];
    const float* bb  = (const float*)d_in[9];
    const float* Wc  = (const float*)d_in[10];
    const float* bc  = (const float*)d_in[11];

    cudaFuncSetAttribute(k_gemm_seg, cudaFuncAttributeMaxDynamicSharedMemorySize, SMEM_BYTES);

    k_gemm_seg<<<NBLK, 256, SMEM_BYTES>>>(x, cid, W1, b1);
    k_reduce<<<64, 256>>>();
    k_head1<<<8, 256>>>(cid, Wf, bf);
    k_head2<<<8, 256>>>(Wa, ba, Wb, bb, Wc, bc);
    k_final<<<1, 256>>>((float*)d_out);
}

// round 3
// speedup vs baseline: 3.4512x; 3.4512x over previous
#include <cuda_runtime.h>
#include <cuda_bf16.h>
#include <cstdint>
#include <math.h>

#define NQ     65536
#define DIMIN  1024
#define DIMH   256
#define NCLUS  8
#define BM     128
#define BK     64
#define NBLK   (NQ / BM)       // 512
#define NITER  (DIMIN / BK)    // 16

// smem layout (bytes)
#define LDA      144           // 64 bf16 (128B) + 16B pad per row
#define STAGE_A  (128 * LDA)   // 18432
#define STAGE_B  (256 * LDA)   // 36864
#define STAGE    (STAGE_A + STAGE_B)
#define OFF_A(s) ((unsigned)(s) * STAGE)
#define OFF_B(s) ((unsigned)(s) * STAGE + STAGE_A)
#define HLD      258
#define OFF_EXTRA 132096u      // 128*258*4  (hbuf region, unioned with stages)
#define OFF_B1   OFF_EXTRA
#define OFF_CID  (OFF_B1 + 1024u)
#define OFF_CNT  (OFF_CID + 512u)
#define SMEM_DYN (OFF_CNT + 64u)

// ---- device scratch (no allocations allowed) ----
__device__ __nv_bfloat16 g_W1bf[DIMH * DIMIN];            // 512 KB
__device__ float g_scratch[2 * NBLK * NCLUS * DIMH];      // 8 MB  [vb][cl][col]
__device__ int   g_scnt[NBLK * NCLUS];
__device__ float g_seg[NCLUS * DIMH];
__device__ int   g_cnt[NCLUS];
__device__ float g_hp[NCLUS * DIMH];
__device__ float g_part[NCLUS * 8];

// ---- helpers ----
__device__ __forceinline__ uint32_t smem_u32(const void* p) {
    uint32_t a;
    asm("{ .reg .u64 t; cvta.to.shared.u64 t, %1; cvt.u32.u64 %0, t; }" : "=r"(a) : "l"(p));
    return a;
}

__device__ __forceinline__ void ldm4(uint32_t* r, uint32_t addr) {
    asm volatile("ldmatrix.sync.aligned.m8n8.x4.shared.b16 {%0,%1,%2,%3}, [%4];"
                 : "=r"(r[0]), "=r"(r[1]), "=r"(r[2]), "=r"(r[3]) : "r"(addr));
}

__device__ __forceinline__ void mma_bf16(float* d, const uint32_t* a,
                                         uint32_t b0, uint32_t b1) {
    asm volatile("mma.sync.aligned.m16n8k16.row.col.f32.bf16.bf16.f32 "
                 "{%0,%1,%2,%3}, {%4,%5,%6,%7}, {%8,%9}, {%0,%1,%2,%3};"
                 : "+f"(d[0]), "+f"(d[1]), "+f"(d[2]), "+f"(d[3])
                 : "r"(a[0]), "r"(a[1]), "r"(a[2]), "r"(a[3]), "r"(b0), "r"(b1));
}

__device__ __forceinline__ void cp_B(uint32_t base, int s, int k0, int tid) {
    uint32_t dst = base + OFF_B(s);
    const char* src = (const char*)g_W1bf + (size_t)k0 * 2;
    #pragma unroll
    for (int i = 0; i < 4; i++) {
        int c  = tid + 512 * i;          // 0..2047
        int n  = c >> 3, kc = c & 7;
        uint32_t d = dst + (unsigned)n * LDA + (unsigned)kc * 16;
        const void* g = src + (size_t)n * (DIMIN * 2) + kc * 16;
        asm volatile("cp.async.cg.shared.global [%0], [%1], 16;" :: "r"(d), "l"(g));
    }
}

__device__ __forceinline__ void ldgA(float4* areg, const float* x,
                                     int row0, int it, int tid) {
    const int r0 = tid >> 4, fc = tid & 15;
    const float* p = x + (size_t)(row0 + r0) * DIMIN + it * BK + fc * 4;
    #pragma unroll
    for (int i = 0; i < 4; i++)
        areg[i] = *(const float4*)(p + (size_t)(32 * i) * DIMIN);
}

__device__ __forceinline__ void stsA(uint32_t sA, const float4* areg, int tid) {
    const int r0 = tid >> 4, fc = tid & 15;
    #pragma unroll
    for (int i = 0; i < 4; i++) {
        __nv_bfloat162 lo = __floats2bfloat162_rn(areg[i].x, areg[i].y);
        __nv_bfloat162 hi = __floats2bfloat162_rn(areg[i].z, areg[i].w);
        uint32_t u0 = *(uint32_t*)&lo, u1 = *(uint32_t*)&hi;
        uint32_t d = sA + (unsigned)(r0 + 32 * i) * LDA + (unsigned)fc * 8;
        asm volatile("st.shared.v2.b32 [%0], {%1,%2};" :: "r"(d), "r"(u0), "r"(u1));
    }
}

// ---------------------------------------------------------------------------
// K0: W1 fp32 -> bf16 (one-time per call, deterministic)
// ---------------------------------------------------------------------------
__global__ __launch_bounds__(256)
void k_w1cvt(const float* __restrict__ W1) {
    int i = (blockIdx.x * 256 + threadIdx.x) * 4;
    float4 v = *(const float4*)(W1 + i);
    __nv_bfloat162 lo = __floats2bfloat162_rn(v.x, v.y);
    __nv_bfloat162 hi = __floats2bfloat162_rn(v.z, v.w);
    uint2 u;
    u.x = *(uint32_t*)&lo;
    u.y = *(uint32_t*)&hi;
    *(uint2*)&g_W1bf[i] = u;
}

// ---------------------------------------------------------------------------
// K1: bf16 mma.sync GEMM  h = relu(x @ W1^T + b1)  fused cluster sums
//     128 rows x 256 cols per CTA, 512 threads (16 warps: 2m x 8n)
// ---------------------------------------------------------------------------
__global__ __launch_bounds__(512)
void k_gemm_seg(const float* __restrict__ x, const int* __restrict__ cid,
                const float* __restrict__ b1)
{
    extern __shared__ char sm[];
    const uint32_t base = smem_u32(sm);
    float* b1s   = (float*)(sm + OFF_B1);
    int*   cid_s = (int*)  (sm + OFF_CID);
    int*   cnt_s = (int*)  (sm + OFF_CNT);

    const int tid  = threadIdx.x;
    const int lane = tid & 31, warp = tid >> 5;
    const int wn = warp & 7, wm = warp >> 3;
    const int row0 = blockIdx.x * BM;

    if (tid < 8)   cnt_s[tid] = 0;
    if (tid < 256) b1s[tid] = b1[tid];
    if (tid < 128) cid_s[tid] = cid[row0 + tid];

    float acc[4][4][4];
    #pragma unroll
    for (int mt = 0; mt < 4; mt++)
        #pragma unroll
        for (int nt = 0; nt < 4; nt++)
            #pragma unroll
            for (int q = 0; q < 4; q++) acc[mt][nt][q] = 0.0f;

    // prologue: stage 0
    float4 areg[4];
    cp_B(base, 0, 0, tid);
    asm volatile("cp.async.commit_group;" ::: "memory");
    ldgA(areg, x, row0, 0, tid);
    stsA(base + OFF_A(0), areg, tid);
    asm volatile("cp.async.wait_group 0;" ::: "memory");
    __syncthreads();

    for (int it = 0; it < NITER; it++) {
        const int s = it & 1;
        if (it + 1 < NITER) {
            cp_B(base, s ^ 1, (it + 1) * BK, tid);
            asm volatile("cp.async.commit_group;" ::: "memory");
            ldgA(areg, x, row0, it + 1, tid);
        }
        const uint32_t sA = base + OFF_A(s), sB = base + OFF_B(s);
        #pragma unroll
        for (int ks = 0; ks < 4; ks++) {
            uint32_t a[4][4];
            const uint32_t abase = sA + (unsigned)(wm * 64 + (lane & 15)) * LDA
                                 + (unsigned)ks * 32 + (unsigned)(lane >> 4) * 16;
            #pragma unroll
            for (int mt = 0; mt < 4; mt++)
                ldm4(a[mt], abase + (unsigned)(mt * 16) * LDA);
            #pragma unroll
            for (int j = 0; j < 2; j++) {
                uint32_t b[4];
                ldm4(b, sB + (unsigned)(wn * 32 + j * 16 + (lane & 15)) * LDA
                          + (unsigned)ks * 32 + (unsigned)(lane >> 4) * 16);
                #pragma unroll
                for (int mt = 0; mt < 4; mt++) {
                    mma_bf16(acc[mt][2 * j],     a[mt], b[0], b[2]);
                    mma_bf16(acc[mt][2 * j + 1], a[mt], b[1], b[3]);
                }
            }
        }
        if (it + 1 < NITER) {
            stsA(base + OFF_A(s ^ 1), areg, tid);
            asm volatile("cp.async.wait_group 0;" ::: "memory");
        }
        __syncthreads();
    }

    // epilogue: accum -> smem hbuf (unioned with stage region)
    float* hbuf = (float*)sm;
    #pragma unroll
    for (int mt = 0; mt < 4; mt++)
        #pragma unroll
        for (int nt = 0; nt < 4; nt++) {
            int gm = wm * 64 + mt * 16 + (lane >> 2);
            int gn = wn * 32 + nt * 8 + 2 * (lane & 3);
            hbuf[gm * HLD + gn]           = acc[mt][nt][0];
            hbuf[gm * HLD + gn + 1]       = acc[mt][nt][1];
            hbuf[(gm + 8) * HLD + gn]     = acc[mt][nt][2];
            hbuf[(gm + 8) * HLD + gn + 1] = acc[mt][nt][3];
        }

    // per-CTA cluster counts (warps 0-3 cover the 128 rows)
    if (tid < 128) {
        int cidv = cid_s[tid];
        #pragma unroll
        for (int c = 0; c < 8; c++) {
            unsigned m = __ballot_sync(0xffffffffu, cidv == c);
            if (lane == c) atomicAdd(&cnt_s[c], __popc(m));
        }
    }
    __syncthreads();

    // bias + relu + cluster-masked column sums: thread = (col, row-half)
    const int ct = tid & 255, rh = tid >> 8;
    const float bt = b1s[ct];
    float sacc[NCLUS];
    #pragma unroll
    for (int c = 0; c < NCLUS; c++) sacc[c] = 0.0f;
    #pragma unroll 4
    for (int r = rh * 64; r < rh * 64 + 64; r++) {
        float v = fmaxf(hbuf[r * HLD + ct] + bt, 0.0f);
        int cd = cid_s[r];
        #pragma unroll
        for (int c = 0; c < NCLUS; c++) sacc[c] += (cd == c) ? v : 0.0f;
    }
    float* outp = g_scratch + ((size_t)blockIdx.x * 2 + rh) * (NCLUS * DIMH) + ct;
    #pragma unroll
    for (int c = 0; c < NCLUS; c++) outp[c * DIMH] = sacc[c];
    if (tid < 8) g_scnt[blockIdx.x * 8 + tid] = cnt_s[tid];
}

// ---------------------------------------------------------------------------
// K2: reduce 1024 virtual-block partials -> g_seg ; counts -> g_cnt
// ---------------------------------------------------------------------------
__global__ __launch_bounds__(256)
void k_reduce()
{
    const int g0 = blockIdx.x * 32;
    const int jj = threadIdx.x & 31;
    const int bs = threadIdx.x >> 5;
    float s = 0.0f;
    #pragma unroll 4
    for (int b = bs; b < 2 * NBLK; b += 8)
        s += g_scratch[(size_t)b * (NCLUS * DIMH) + g0 + jj];
    __shared__ float red[8][33];
    __shared__ int   credp[8][9];
    red[bs][jj] = s;
    if (blockIdx.x == 0 && threadIdx.x < 64) {
        int c = threadIdx.x & 7, sl = threadIdx.x >> 3, t = 0;
        for (int b = sl; b < NBLK; b += 8) t += g_scnt[b * 8 + c];
        credp[c][sl] = t;
    }
    __syncthreads();
    if (bs == 0) {
        float t = 0.0f;
        #pragma unroll
        for (int c = 0; c < 8; c++) t += red[c][jj];
        g_seg[g0 + jj] = t;
    }
    if (blockIdx.x == 0 && threadIdx.x < 8) {
        int T = 0;
        #pragma unroll
        for (int sl = 0; sl < 8; sl++) T += credp[threadIdx.x][sl];
        g_cnt[threadIdx.x] = T;
    }
}

// ---------------------------------------------------------------------------
// K3a: cluster means + h_path = relu(hc @ Wf^T + bf)     grid 8 x 256
// ---------------------------------------------------------------------------
__global__ __launch_bounds__(256)
void k_head1(const float* __restrict__ Wf, const float* __restrict__ bfv)
{
    const int c = blockIdx.x, tid = threadIdx.x;
    __shared__ float hc_s[DIMH];
    float denom = fmaxf((float)g_cnt[c], 1.0f);
    hc_s[tid] = g_seg[c * DIMH + tid] / denom;
    __syncthreads();

    float a = bfv[tid];
    const float4* w = (const float4*)(Wf + (size_t)tid * DIMH);
    #pragma unroll 8
    for (int k = 0; k < DIMH / 4; k++) {
        float4 wv = w[k];
        a += wv.x * hc_s[4 * k]     + wv.y * hc_s[4 * k + 1]
           + wv.z * hc_s[4 * k + 2] + wv.w * hc_s[4 * k + 3];
    }
    g_hp[c * DIMH + tid] = fmaxf(a, 0.0f);
}

// ---------------------------------------------------------------------------
// K3b: gated attention partial logits   grid 64 (8 clus x 8 row-groups)
// ---------------------------------------------------------------------------
__global__ __launch_bounds__(256)
void k_head2(const float* __restrict__ Wa, const float* __restrict__ ba,
             const float* __restrict__ Wb, const float* __restrict__ bb,
             const float* __restrict__ Wc)
{
    const int b = blockIdx.x, tid = threadIdx.x;
    const int c = b >> 3, rg = b & 7;
    __shared__ float hp_s[DIMH];
    hp_s[tid] = g_hp[c * DIMH + tid];
    __syncthreads();

    const int row = rg * 32 + (tid >> 3);
    const int k0  = (tid & 7) * 32;
    const float4* wa = (const float4*)(Wa + (size_t)row * DIMH + k0);
    const float4* wb = (const float4*)(Wb + (size_t)row * DIMH + k0);
    float aa = 0.0f, gg = 0.0f;
    #pragma unroll
    for (int k = 0; k < 8; k++) {
        float4 av = wa[k], bv = wb[k];
        float h0 = hp_s[k0 + 4 * k], h1 = hp_s[k0 + 4 * k + 1];
        float h2 = hp_s[k0 + 4 * k + 2], h3 = hp_s[k0 + 4 * k + 3];
        aa += av.x * h0 + av.y * h1 + av.z * h2 + av.w * h3;
        gg += bv.x * h0 + bv.y * h1 + bv.z * h2 + bv.w * h3;
    }
    #pragma unroll
    for (int o = 4; o > 0; o >>= 1) {
        aa += __shfl_xor_sync(0xffffffffu, aa, o);
        gg += __shfl_xor_sync(0xffffffffu, gg, o);
    }
    float val = 0.0f;
    if ((tid & 7) == 0) {
        aa += ba[row]; gg += bb[row];
        val = tanhf(aa) * (1.0f / (1.0f + expf(-gg))) * Wc[row];
    }
    val += __shfl_xor_sync(0xffffffffu, val, 8);
    val += __shfl_xor_sync(0xffffffffu, val, 16);
    __shared__ float wred[8];
    if ((tid & 31) == 0) wred[tid >> 5] = val;
    __syncthreads();
    if (tid == 0) {
        float t = 0.0f;
        #pragma unroll
        for (int w = 0; w < 8; w++) t += wred[w];
        g_part[c * 8 + rg] = t;
    }
}

// ---------------------------------------------------------------------------
// K3c: softmax over 8 logits + weighted sum -> out[256]
// ---------------------------------------------------------------------------
__global__ __launch_bounds__(256)
void k_final(const float* __restrict__ bc, float* __restrict__ out)
{
    const int tid = threadIdx.x;
    float l[NCLUS];
    #pragma unroll
    for (int c = 0; c < NCLUS; c++) {
        float t = bc[0];
        #pragma unroll
        for (int g = 0; g < 8; g++) t += g_part[c * 8 + g];
        l[c] = t;
    }
    float m = -1e30f;
    #pragma unroll
    for (int c = 0; c < NCLUS; c++) m = fmaxf(m, l[c]);
    float S = 0.0f;
    #pragma unroll
    for (int c = 0; c < NCLUS; c++) { l[c] = expf(l[c] - m); S += l[c]; }
    float o = 0.0f;
    #pragma unroll
    for (int c = 0; c < NCLUS; c++) o += l[c] * g_hp[c * DIMH + tid];
    out[tid] = o / S;
}

// ---------------------------------------------------------------------------
extern "C" void kernel_launch(void* const* d_in, const int* in_sizes, int n_in,
                              void* d_out, int out_size)
{
    const float* x   = (const float*)d_in[0];
    const int*   cid = (const int*)  d_in[1];
    const float* W1  = (const float*)d_in[2];
    const float* b1  = (const float*)d_in[3];
    const float* Wf  = (const float*)d_in[4];
    const float* bf  = (const float*)d_in[5];
    const float* Wa  = (const float*)d_in[6];
    const float* ba  = (const float*)d_in[7];
    const float* Wb  = (const float*)d_in[8];
    const float* bb  = (const float*)d_in[9];
    const float* Wc  = (const float*)d_in[10];
    const float* bc  = (const float*)d_in[11];

    cudaFuncSetAttribute(k_gemm_seg, cudaFuncAttributeMaxDynamicSharedMemorySize, SMEM_DYN);

    k_w1cvt<<<256, 256>>>(W1);
    k_gemm_seg<<<NBLK, 512, SMEM_DYN>>>(x, cid, b1);
    k_reduce<<<64, 256>>>();
    k_head1<<<8, 256>>>(Wf, bf);
    k_head2<<<64, 256>>>(Wa, ba, Wb, bb, Wc);
    k_final<<<1, 256>>>(bc, (float*)d_out);
}